// round 6
// baseline (speedup 1.0000x reference)
#include <cuda_runtime.h>
#include <cuda_fp16.h>
#include <cuda_bf16.h>
#include <cstdint>

// ---------------------------------------------------------------------------
// InversionModel R6: fp16 mma.sync GEMM, 128x256 CTA tile, 64x64 warp tiles,
// ldmatrix.x4 fragments, 5-stage cp.async pipeline (FIXED stage rotation).
// ---------------------------------------------------------------------------

#define BM 128
#define BN 256
#define BK 32
#define STAGES 5
#define LDSK (BK + 8)          // 40 halves per row
#define ALDB (LDSK * 2)        // 80 bytes per smem row
#define M_DIM 2048
#define N_DIM 6432
#define K_DIM 6432
#define SMEM_BYTES (STAGES * (BM + BN) * LDSK * (int)sizeof(__half))   // 153600

// Scratch (static device arrays; no allocation allowed)
__device__ __align__(16) __half g_act0[(size_t)M_DIM * N_DIM];
__device__ __align__(16) __half g_act1[(size_t)M_DIM * N_DIM];
__device__ __align__(16) __half g_wh[(size_t)N_DIM * K_DIM];

// ------------------------------ helpers ------------------------------------

__device__ __forceinline__ void cp16(void* dst, const void* src, bool pred) {
    uint32_t s = (uint32_t)__cvta_generic_to_shared(dst);
    int sz = pred ? 16 : 0;
    asm volatile("cp.async.cg.shared.global [%0], [%1], 16, %2;\n"
                 :: "r"(s), "l"(src), "r"(sz));
}

__device__ __forceinline__ void mma16816(float* c, const uint32_t* a, const uint32_t* b) {
    asm volatile(
        "mma.sync.aligned.m16n8k16.row.col.f32.f16.f16.f32 "
        "{%0,%1,%2,%3}, {%4,%5,%6,%7}, {%8,%9}, {%0,%1,%2,%3};\n"
        : "+f"(c[0]), "+f"(c[1]), "+f"(c[2]), "+f"(c[3])
        : "r"(a[0]), "r"(a[1]), "r"(a[2]), "r"(a[3]), "r"(b[0]), "r"(b[1]));
}

__device__ __forceinline__ void ldsm4(uint32_t& r0, uint32_t& r1, uint32_t& r2,
                                      uint32_t& r3, uint32_t addr) {
    asm volatile("ldmatrix.sync.aligned.m8n8.x4.shared.b16 {%0,%1,%2,%3}, [%4];\n"
                 : "=r"(r0), "=r"(r1), "=r"(r2), "=r"(r3) : "r"(addr));
}

// ------------------------- weight fp32 -> fp16 ------------------------------

__global__ void convert_w_kernel(const float* __restrict__ w, __half* __restrict__ wh,
                                 long long n) {
    long long i = ((long long)blockIdx.x * blockDim.x + threadIdx.x) * 4;
    if (i < n) {
        float4 v = *(const float4*)(w + i);
        *(__half2*)(wh + i)     = __floats2half2_rn(v.x, v.y);
        *(__half2*)(wh + i + 2) = __floats2half2_rn(v.z, v.w);
    }
}

// ------------------------------ frontend -----------------------------------

__global__ void frontend_kernel(const float* __restrict__ x,
                                const float* __restrict__ w1, const float* __restrict__ b1,
                                const float* __restrict__ w2, const float* __restrict__ b2,
                                __half* __restrict__ f) {
    int b = blockIdx.x;
    int sidx = blockIdx.y;           // 0,1,2 -> s = 1,2,4
    int s = 1 << sidx;
    int Lc = 480 >> sidx;
    int off = (sidx == 0) ? 0 : (sidx == 1 ? 117 : 174);

    __shared__ float xc[4 * 480];
    __shared__ float p1[16 * 238];
    __shared__ float w1s[320], w2s[2560];
    __shared__ float b1s[16], b2s[32];

    int tid = threadIdx.x;           // 128 threads
    for (int i = tid; i < 320; i += 128) w1s[i] = w1[i];
    for (int i = tid; i < 2560; i += 128) w2s[i] = w2[i];
    if (tid < 16) b1s[tid] = b1[tid];
    if (tid < 32) b2s[tid] = b2[tid];

    const float* xb = x + (size_t)b * 4 * 480;
    float inv_s = 1.0f / (float)s;
    for (int i = tid; i < 4 * Lc; i += 128) {
        int c = i / Lc, p = i % Lc;
        float sum = 0.f;
        for (int j = 0; j < s; ++j) sum += xb[c * 480 + p * s + j];
        xc[c * Lc + p] = sum * inv_s;
    }
    __syncthreads();

    int L1 = Lc - 4;
    int L1p = L1 >> 1;               // 238 / 118 / 58
    for (int i = tid; i < 16 * L1p; i += 128) {
        int o = i / L1p, q = i % L1p;
        float best = -1e30f;
        #pragma unroll
        for (int pp = 0; pp < 2; ++pp) {
            int p = 2 * q + pp;
            float acc = b1s[o];
            #pragma unroll
            for (int c = 0; c < 4; ++c)
                #pragma unroll
                for (int k = 0; k < 5; ++k)
                    acc += xc[c * Lc + p + k] * w1s[o * 20 + c * 5 + k];
            best = fmaxf(best, acc);
        }
        p1[o * L1p + q] = fmaxf(best, 0.f);
    }
    __syncthreads();

    int L2 = (L1p - 4) >> 1;         // 117 / 57 / 27
    __half* fb = f + (size_t)b * N_DIM;
    for (int i = tid; i < 32 * L2; i += 128) {
        int o2 = i / L2, q = i % L2;
        float best = -1e30f;
        #pragma unroll
        for (int pp = 0; pp < 2; ++pp) {
            int p = 2 * q + pp;
            float acc = b2s[o2];
            #pragma unroll
            for (int c1 = 0; c1 < 16; ++c1)
                #pragma unroll
                for (int k = 0; k < 5; ++k)
                    acc += p1[c1 * L1p + p + k] * w2s[o2 * 80 + c1 * 5 + k];
            best = fmaxf(best, acc);
        }
        fb[o2 * 201 + off + q] = __float2half_rn(fmaxf(best, 0.f));
    }
}

// ------------------------------- GEMM --------------------------------------
// Out[m,n] = relu( sum_k A[m,k]*W[n,k] + bias[n] ), fp16 in, fp32 acc, fp16 out.
// 128x256x32 CTA tiles, 8 warps (2x4), warp tile 64x64, ldmatrix.x4 loads.

extern __shared__ __half dynsmem[];

__global__ __launch_bounds__(256, 1)
void gemm_relu_kernel(const __half* __restrict__ A, const __half* __restrict__ W,
                      const float* __restrict__ bias, __half* __restrict__ Out) {
    __half* sA = dynsmem;                                  // [STAGES][BM][LDSK]
    __half* sB = dynsmem + STAGES * BM * LDSK;             // [STAGES][BN][LDSK]
#define AS(st, r, c) sA[((st) * BM + (r)) * LDSK + (c)]
#define BS(st, r, c) sB[((st) * BN + (r)) * LDSK + (c)]

    const int tid = threadIdx.x;
    const int bm = blockIdx.y * BM;
    const int bn = blockIdx.x * BN;
    const int warp = tid >> 5, lane = tid & 31;
    const int wm = (warp >> 2) * 64;       // 0 or 64
    const int wn = (warp & 3) * 64;        // 0,64,128,192
    const int g = lane >> 2, tg = lane & 3;

    const int lrow = tid >> 2;          // 0..63
    const int lcol = (tid & 3) * 8;     // 0,8,16,24

    const __half* Ag = A + (size_t)(bm + lrow) * K_DIM + lcol;
    const size_t R64 = (size_t)64 * K_DIM;
    // B rows bn+lrow+64*i (i=0..3); clamp row, pred load (zero-fill). Cols
    // >= N_DIM never reach the output: epilogue masks col < N_DIM.
    bool bv[4];
    const __half* Wg[4];
    #pragma unroll
    for (int i = 0; i < 4; ++i) {
        int nrow = bn + lrow + 64 * i;
        bv[i] = nrow < N_DIM;
        Wg[i] = W + (size_t)(bv[i] ? nrow : N_DIM - 1) * K_DIM + lcol;
    }

#define LOAD_STAGE(st, k0) do {                                \
        cp16(&AS(st, lrow, lcol),      Ag + (k0), true);       \
        cp16(&AS(st, lrow + 64, lcol), Ag + R64 + (k0), true); \
        _Pragma("unroll")                                      \
        for (int _i = 0; _i < 4; ++_i)                         \
            cp16(&BS(st, lrow + 64 * _i, lcol), Wg[_i] + (k0), bv[_i]); \
    } while (0)

    // ldmatrix per-lane base offsets (bytes, shared space)
    const uint32_t sAu = (uint32_t)__cvta_generic_to_shared(sA);
    const uint32_t sBu = (uint32_t)__cvta_generic_to_shared(sB);
    const uint32_t a_off = (uint32_t)((wm + (lane & 15)) * ALDB + (lane >> 4) * 16);
    const uint32_t b_off = (uint32_t)((wn + (lane >> 4) * 8 + (lane & 7)) * ALDB
                                      + ((lane >> 3) & 1) * 16);

    float acc[4][8][4];
    #pragma unroll
    for (int mt = 0; mt < 4; ++mt)
        #pragma unroll
        for (int nt = 0; nt < 8; ++nt)
            #pragma unroll
            for (int i = 0; i < 4; ++i) acc[mt][nt][i] = 0.f;

    #pragma unroll
    for (int st = 0; st < STAGES - 1; ++st) {
        LOAD_STAGE(st, st * BK);
        asm volatile("cp.async.commit_group;\n");
    }

    const int NK = K_DIM / BK;   // 201
    int st = 0, stn = STAGES - 1;
    for (int kt = 0; kt < NK; ++kt) {
        asm volatile("cp.async.wait_group %0;\n" :: "n"(STAGES - 2));
        __syncthreads();
        int knext = kt + STAGES - 1;
        if (knext < NK) LOAD_STAGE(stn, knext * BK);
        asm volatile("cp.async.commit_group;\n");

        const uint32_t aS = sAu + (uint32_t)(st * BM * ALDB) + a_off;
        const uint32_t bS = sBu + (uint32_t)(st * BN * ALDB) + b_off;

        #pragma unroll
        for (int ks = 0; ks < 2; ++ks) {
            uint32_t afr[4][4], bfr[8][2];
            const uint32_t ak = aS + ks * 32;    // ks*16 halves
            const uint32_t bk = bS + ks * 32;
            #pragma unroll
            for (int mt = 0; mt < 4; ++mt)
                ldsm4(afr[mt][0], afr[mt][1], afr[mt][2], afr[mt][3],
                      ak + mt * 16 * ALDB);
            #pragma unroll
            for (int p = 0; p < 4; ++p)
                ldsm4(bfr[2 * p][0], bfr[2 * p][1], bfr[2 * p + 1][0], bfr[2 * p + 1][1],
                      bk + p * 16 * ALDB);
            #pragma unroll
            for (int mt = 0; mt < 4; ++mt)
                #pragma unroll
                for (int nt = 0; nt < 8; ++nt)
                    mma16816(acc[mt][nt], afr[mt], bfr[nt]);
        }
        // advance compute and load stages INDEPENDENTLY (R5 bug: st = stn)
        if (++st == STAGES) st = 0;
        if (++stn == STAGES) stn = 0;
    }

    // Epilogue: bias + relu + fp16 store
    #pragma unroll
    for (int mt = 0; mt < 4; ++mt) {
        int row = bm + wm + mt * 16 + g;
        #pragma unroll
        for (int nt = 0; nt < 8; ++nt) {
            int col = bn + wn + nt * 8 + tg * 2;
            if (col < N_DIM) {
                float2 bb = *(const float2*)(bias + col);
                float v0a = fmaxf(acc[mt][nt][0] + bb.x, 0.f);
                float v1a = fmaxf(acc[mt][nt][1] + bb.y, 0.f);
                float v2a = fmaxf(acc[mt][nt][2] + bb.x, 0.f);
                float v3a = fmaxf(acc[mt][nt][3] + bb.y, 0.f);
                *(__half2*)(Out + (size_t)row * N_DIM + col)       = __floats2half2_rn(v0a, v1a);
                *(__half2*)(Out + (size_t)(row + 8) * N_DIM + col) = __floats2half2_rn(v2a, v3a);
            }
        }
    }
#undef AS
#undef BS
#undef LOAD_STAGE
}

// ------------------------------- head --------------------------------------

__global__ void head_kernel(const __half* __restrict__ f, const float* __restrict__ wo,
                            const float* __restrict__ bo, float* __restrict__ out) {
    int b = blockIdx.x;
    int w = threadIdx.x >> 5;        // 0..4
    int lane = threadIdx.x & 31;
    const __half* fb = f + (size_t)b * N_DIM;
    const float* wr = wo + (size_t)w * N_DIM;
    float acc = 0.f;
    for (int k = lane * 2; k < N_DIM; k += 64) {
        __half2 h = *(const __half2*)(fb + k);
        float2 wv = *(const float2*)(wr + k);
        acc += __half2float(h.x) * wv.x + __half2float(h.y) * wv.y;
    }
    #pragma unroll
    for (int o = 16; o > 0; o >>= 1) acc += __shfl_xor_sync(0xffffffffu, acc, o);
    if (lane == 0) out[b * 5 + w] = acc + bo[w];
}

// ------------------------------ launch -------------------------------------

extern "C" void kernel_launch(void* const* d_in, const int* in_sizes, int n_in,
                              void* d_out, int out_size) {
    (void)in_sizes; (void)n_in; (void)out_size;
    const float* x  = (const float*)d_in[0];
    const float* w1 = (const float*)d_in[1];
    const float* b1 = (const float*)d_in[2];
    const float* w2 = (const float*)d_in[3];
    const float* b2 = (const float*)d_in[4];
    const float* wl = (const float*)d_in[5];
    const float* bl = (const float*)d_in[6];
    const float* wo = (const float*)d_in[7];
    const float* bo = (const float*)d_in[8];
    float* out = (float*)d_out;

    __half *fa, *fb, *wh;
    cudaGetSymbolAddress((void**)&fa, g_act0);
    cudaGetSymbolAddress((void**)&fb, g_act1);
    cudaGetSymbolAddress((void**)&wh, g_wh);

    // weight conversion (fp32 -> fp16), 41,370,624 elements
    long long nW = (long long)N_DIM * K_DIM;
    convert_w_kernel<<<(unsigned)((nW / 4 + 255) / 256), 256>>>(wl, wh, nW);

    // frontend: (batch, scale) blocks
    frontend_kernel<<<dim3(2048, 3), 128>>>(x, w1, b1, w2, b2, fa);

    cudaFuncSetAttribute(gemm_relu_kernel,
                         cudaFuncAttributeMaxDynamicSharedMemorySize, SMEM_BYTES);
    dim3 grid((N_DIM + BN - 1) / BN, M_DIM / BM);   // (26, 16) = 416 CTAs
    gemm_relu_kernel<<<grid, 256, SMEM_BYTES>>>(fa, wh, bl, fb);
    gemm_relu_kernel<<<grid, 256, SMEM_BYTES>>>(fb, wh, bl, fa);
    gemm_relu_kernel<<<grid, 256, SMEM_BYTES>>>(fa, wh, bl, fb);
    gemm_relu_kernel<<<grid, 256, SMEM_BYTES>>>(fb, wh, bl, fa);

    head_kernel<<<2048, 160>>>(fa, wo, bo, out);
}

// round 7
// speedup vs baseline: 1.1538x; 1.1538x over previous
#include <cuda_runtime.h>
#include <cuda_fp16.h>
#include <cuda_bf16.h>
#include <cstdint>

// ---------------------------------------------------------------------------
// InversionModel R7: fp16 mma.sync GEMM, 128x128x32 tiles, warp 64x32,
// CUTLASS-sm80-style double-buffered register fragments: LDSM always one
// MMA-batch ahead, barrier mid-iteration, cross-tile fragment prefetch.
// ---------------------------------------------------------------------------

#define BM 128
#define BN 128
#define BK 32
#define STAGES 4
#define LDSK (BK + 8)          // 40 halves per row
#define ALDB (LDSK * 2)        // 80 bytes per smem row
#define M_DIM 2048
#define N_DIM 6432
#define K_DIM 6432
#define SMEM_BYTES (2 * STAGES * BM * LDSK * (int)sizeof(__half))   // 81920

// Scratch (static device arrays; no allocation allowed)
__device__ __align__(16) __half g_act0[(size_t)M_DIM * N_DIM];
__device__ __align__(16) __half g_act1[(size_t)M_DIM * N_DIM];
__device__ __align__(16) __half g_wh[(size_t)N_DIM * K_DIM];

// ------------------------------ helpers ------------------------------------

__device__ __forceinline__ void cp16(void* dst, const void* src, bool pred) {
    uint32_t s = (uint32_t)__cvta_generic_to_shared(dst);
    int sz = pred ? 16 : 0;
    asm volatile("cp.async.cg.shared.global [%0], [%1], 16, %2;\n"
                 :: "r"(s), "l"(src), "r"(sz));
}

__device__ __forceinline__ void mma16816(float* c, const uint32_t* a, const uint32_t* b) {
    asm volatile(
        "mma.sync.aligned.m16n8k16.row.col.f32.f16.f16.f32 "
        "{%0,%1,%2,%3}, {%4,%5,%6,%7}, {%8,%9}, {%0,%1,%2,%3};\n"
        : "+f"(c[0]), "+f"(c[1]), "+f"(c[2]), "+f"(c[3])
        : "r"(a[0]), "r"(a[1]), "r"(a[2]), "r"(a[3]), "r"(b[0]), "r"(b[1]));
}

__device__ __forceinline__ void ldsm4(uint32_t& r0, uint32_t& r1, uint32_t& r2,
                                      uint32_t& r3, uint32_t addr) {
    asm volatile("ldmatrix.sync.aligned.m8n8.x4.shared.b16 {%0,%1,%2,%3}, [%4];\n"
                 : "=r"(r0), "=r"(r1), "=r"(r2), "=r"(r3) : "r"(addr));
}

// ------------------------- weight fp32 -> fp16 ------------------------------

__global__ void convert_w_kernel(const float* __restrict__ w, __half* __restrict__ wh,
                                 long long n) {
    long long i = ((long long)blockIdx.x * blockDim.x + threadIdx.x) * 8;
    if (i < n) {
        float4 a = *(const float4*)(w + i);
        float4 b = *(const float4*)(w + i + 4);
        __half2 h0 = __floats2half2_rn(a.x, a.y);
        __half2 h1 = __floats2half2_rn(a.z, a.w);
        __half2 h2 = __floats2half2_rn(b.x, b.y);
        __half2 h3 = __floats2half2_rn(b.z, b.w);
        *(uint4*)(wh + i) = make_uint4(*(uint32_t*)&h0, *(uint32_t*)&h1,
                                       *(uint32_t*)&h2, *(uint32_t*)&h3);
    }
}

// ------------------------------ frontend -----------------------------------

__global__ void frontend_kernel(const float* __restrict__ x,
                                const float* __restrict__ w1, const float* __restrict__ b1,
                                const float* __restrict__ w2, const float* __restrict__ b2,
                                __half* __restrict__ f) {
    int b = blockIdx.x;
    int sidx = blockIdx.y;           // 0,1,2 -> s = 1,2,4
    int s = 1 << sidx;
    int Lc = 480 >> sidx;
    int off = (sidx == 0) ? 0 : (sidx == 1 ? 117 : 174);

    __shared__ float xc[4 * 480];
    __shared__ float p1[16 * 238];
    __shared__ float w1s[320], w2s[2560];
    __shared__ float b1s[16], b2s[32];

    int tid = threadIdx.x;           // 128 threads
    for (int i = tid; i < 320; i += 128) w1s[i] = w1[i];
    for (int i = tid; i < 2560; i += 128) w2s[i] = w2[i];
    if (tid < 16) b1s[tid] = b1[tid];
    if (tid < 32) b2s[tid] = b2[tid];

    const float* xb = x + (size_t)b * 4 * 480;
    float inv_s = 1.0f / (float)s;
    for (int i = tid; i < 4 * Lc; i += 128) {
        int c = i / Lc, p = i % Lc;
        float sum = 0.f;
        for (int j = 0; j < s; ++j) sum += xb[c * 480 + p * s + j];
        xc[c * Lc + p] = sum * inv_s;
    }
    __syncthreads();

    int L1 = Lc - 4;
    int L1p = L1 >> 1;               // 238 / 118 / 58
    for (int i = tid; i < 16 * L1p; i += 128) {
        int o = i / L1p, q = i % L1p;
        float best = -1e30f;
        #pragma unroll
        for (int pp = 0; pp < 2; ++pp) {
            int p = 2 * q + pp;
            float acc = b1s[o];
            #pragma unroll
            for (int c = 0; c < 4; ++c)
                #pragma unroll
                for (int k = 0; k < 5; ++k)
                    acc += xc[c * Lc + p + k] * w1s[o * 20 + c * 5 + k];
            best = fmaxf(best, acc);
        }
        p1[o * L1p + q] = fmaxf(best, 0.f);
    }
    __syncthreads();

    int L2 = (L1p - 4) >> 1;         // 117 / 57 / 27
    __half* fb = f + (size_t)b * N_DIM;
    for (int i = tid; i < 32 * L2; i += 128) {
        int o2 = i / L2, q = i % L2;
        float best = -1e30f;
        #pragma unroll
        for (int pp = 0; pp < 2; ++pp) {
            int p = 2 * q + pp;
            float acc = b2s[o2];
            #pragma unroll
            for (int c1 = 0; c1 < 16; ++c1)
                #pragma unroll
                for (int k = 0; k < 5; ++k)
                    acc += p1[c1 * L1p + p + k] * w2s[o2 * 80 + c1 * 5 + k];
            best = fmaxf(best, acc);
        }
        fb[o2 * 201 + off + q] = __float2half_rn(fmaxf(best, 0.f));
    }
}

// ------------------------------- GEMM --------------------------------------
// Out[m,n] = relu( sum_k A[m,k]*W[n,k] + bias[n] ), fp16 in, fp32 acc, fp16 out.
// 128x128x32 tiles, 8 warps (2x4), warp tile 64x32, double-buffered fragments.

extern __shared__ __half dynsmem[];

__global__ __launch_bounds__(256, 2)
void gemm_relu_kernel(const __half* __restrict__ A, const __half* __restrict__ W,
                      const float* __restrict__ bias, __half* __restrict__ Out) {
    __half* sA = dynsmem;                                  // [STAGES][BM][LDSK]
    __half* sB = dynsmem + STAGES * BM * LDSK;             // [STAGES][BN][LDSK]
#define AS(st, r, c) sA[((st) * BM + (r)) * LDSK + (c)]
#define BS(st, r, c) sB[((st) * BN + (r)) * LDSK + (c)]

    const int tid = threadIdx.x;
    const int bm = blockIdx.y * BM;
    const int bn = blockIdx.x * BN;
    const int warp = tid >> 5, lane = tid & 31;
    const int wm = (warp >> 2) * 64;
    const int wn = (warp & 3) * 32;
    const int g = lane >> 2, tg = lane & 3;

    const int lrow = tid >> 2;          // 0..63
    const int lcol = (tid & 3) * 8;     // 0,8,16,24

    const __half* Ag = A + (size_t)(bm + lrow) * K_DIM + lcol;
    const size_t R64 = (size_t)64 * K_DIM;
    int nrow0 = bn + lrow, nrow1 = bn + lrow + 64;
    bool v0 = nrow0 < N_DIM, v1 = nrow1 < N_DIM;
    const __half* Wg0 = W + (size_t)(v0 ? nrow0 : N_DIM - 1) * K_DIM + lcol;
    const __half* Wg1 = W + (size_t)(v1 ? nrow1 : N_DIM - 1) * K_DIM + lcol;

#define LOAD_STAGE(st, k0) do {                                \
        cp16(&AS(st, lrow, lcol),      Ag + (k0), true);       \
        cp16(&AS(st, lrow + 64, lcol), Ag + R64 + (k0), true); \
        cp16(&BS(st, lrow, lcol),      Wg0 + (k0), v0);        \
        cp16(&BS(st, lrow + 64, lcol), Wg1 + (k0), v1);        \
    } while (0)

    // ldmatrix per-lane base offsets (bytes, shared space)
    const uint32_t sAu = (uint32_t)__cvta_generic_to_shared(sA);
    const uint32_t sBu = (uint32_t)__cvta_generic_to_shared(sB);
    const uint32_t a_off = (uint32_t)((wm + (lane & 15)) * ALDB + (lane >> 4) * 16);
    const uint32_t b_off = (uint32_t)((wn + (lane >> 4) * 8 + (lane & 7)) * ALDB
                                      + ((lane >> 3) & 1) * 16);

    // Fragment loads for one k-halftile (16 K): 4 A-ldsm4 + 2 B-ldsm4
#define LD_FRAGS(buf, aaddr, baddr) do {                                       \
        _Pragma("unroll")                                                      \
        for (int _mt = 0; _mt < 4; ++_mt)                                      \
            ldsm4(afr[buf][_mt][0], afr[buf][_mt][1], afr[buf][_mt][2],        \
                  afr[buf][_mt][3], (aaddr) + _mt * 16 * ALDB);                \
        ldsm4(bfr[buf][0][0], bfr[buf][0][1], bfr[buf][1][0], bfr[buf][1][1],  \
              (baddr));                                                        \
        ldsm4(bfr[buf][2][0], bfr[buf][2][1], bfr[buf][3][0], bfr[buf][3][1],  \
              (baddr) + 16 * ALDB);                                            \
    } while (0)

#define MMA_BATCH(buf) do {                                                    \
        _Pragma("unroll")                                                      \
        for (int _mt = 0; _mt < 4; ++_mt)                                      \
            _Pragma("unroll")                                                  \
            for (int _nt = 0; _nt < 4; ++_nt)                                  \
                mma16816(acc[_mt][_nt], afr[buf][_mt], bfr[buf][_nt]);         \
    } while (0)

    float acc[4][4][4];
    #pragma unroll
    for (int mt = 0; mt < 4; ++mt)
        #pragma unroll
        for (int nt = 0; nt < 4; ++nt)
            #pragma unroll
            for (int i = 0; i < 4; ++i) acc[mt][nt][i] = 0.f;

    uint32_t afr[2][4][4], bfr[2][4][2];

    // prologue: fill stages 0..2
    #pragma unroll
    for (int st = 0; st < STAGES - 1; ++st) {
        LOAD_STAGE(st, st * BK);
        asm volatile("cp.async.commit_group;\n");
    }
    asm volatile("cp.async.wait_group %0;\n" :: "n"(STAGES - 2));
    __syncthreads();

    uint32_t aS = sAu + a_off;          // stage 0
    uint32_t bS = sBu + b_off;
    LD_FRAGS(0, aS, bS);                // tile 0, ks=0

    const int NK = K_DIM / BK;   // 201
    int st = 0;
    #pragma unroll 1
    for (int kt = 0; kt < NK; ++kt) {
        // ks=1 frags of current tile (one batch ahead)
        LD_FRAGS(1, aS + 32, bS + 32);
        MMA_BATCH(0);

        // issue next stage's global loads
        int knext = kt + STAGES - 1;
        if (knext < NK) LOAD_STAGE(knext & (STAGES - 1), knext * BK);
        asm volatile("cp.async.commit_group;\n");
        asm volatile("cp.async.wait_group %0;\n" :: "n"(STAGES - 2));
        __syncthreads();

        // prefetch next tile's ks=0 frags (stage st+1 is ready: wait_group(2)
        // with kt+4 groups committed completes stages through kt+1)
        int st1 = (st + 1) & (STAGES - 1);
        uint32_t aS1 = sAu + (uint32_t)(st1 * BM * ALDB) + a_off;
        uint32_t bS1 = sBu + (uint32_t)(st1 * BN * ALDB) + b_off;
        LD_FRAGS(0, aS1, bS1);          // harmless garbage on final iteration
        MMA_BATCH(1);

        st = st1; aS = aS1; bS = bS1;
    }

    // Epilogue: bias + relu + fp16 store
    #pragma unroll
    for (int mt = 0; mt < 4; ++mt) {
        int row = bm + wm + mt * 16 + g;
        #pragma unroll
        for (int nt = 0; nt < 4; ++nt) {
            int col = bn + wn + nt * 8 + tg * 2;
            if (col < N_DIM) {
                float2 bb = *(const float2*)(bias + col);
                float v0a = fmaxf(acc[mt][nt][0] + bb.x, 0.f);
                float v1a = fmaxf(acc[mt][nt][1] + bb.y, 0.f);
                float v2a = fmaxf(acc[mt][nt][2] + bb.x, 0.f);
                float v3a = fmaxf(acc[mt][nt][3] + bb.y, 0.f);
                *(__half2*)(Out + (size_t)row * N_DIM + col)       = __floats2half2_rn(v0a, v1a);
                *(__half2*)(Out + (size_t)(row + 8) * N_DIM + col) = __floats2half2_rn(v2a, v3a);
            }
        }
    }
#undef AS
#undef BS
#undef LOAD_STAGE
#undef LD_FRAGS
#undef MMA_BATCH
}

// ------------------------------- head --------------------------------------

__global__ void head_kernel(const __half* __restrict__ f, const float* __restrict__ wo,
                            const float* __restrict__ bo, float* __restrict__ out) {
    int b = blockIdx.x;
    int w = threadIdx.x >> 5;        // 0..4
    int lane = threadIdx.x & 31;
    const __half* fb = f + (size_t)b * N_DIM;
    const float* wr = wo + (size_t)w * N_DIM;
    float acc = 0.f;
    for (int k = lane * 2; k < N_DIM; k += 64) {
        __half2 h = *(const __half2*)(fb + k);
        float2 wv = *(const float2*)(wr + k);
        acc += __half2float(h.x) * wv.x + __half2float(h.y) * wv.y;
    }
    #pragma unroll
    for (int o = 16; o > 0; o >>= 1) acc += __shfl_xor_sync(0xffffffffu, acc, o);
    if (lane == 0) out[b * 5 + w] = acc + bo[w];
}

// ------------------------------ launch -------------------------------------

extern "C" void kernel_launch(void* const* d_in, const int* in_sizes, int n_in,
                              void* d_out, int out_size) {
    (void)in_sizes; (void)n_in; (void)out_size;
    const float* x  = (const float*)d_in[0];
    const float* w1 = (const float*)d_in[1];
    const float* b1 = (const float*)d_in[2];
    const float* w2 = (const float*)d_in[3];
    const float* b2 = (const float*)d_in[4];
    const float* wl = (const float*)d_in[5];
    const float* bl = (const float*)d_in[6];
    const float* wo = (const float*)d_in[7];
    const float* bo = (const float*)d_in[8];
    float* out = (float*)d_out;

    __half *fa, *fb, *wh;
    cudaGetSymbolAddress((void**)&fa, g_act0);
    cudaGetSymbolAddress((void**)&fb, g_act1);
    cudaGetSymbolAddress((void**)&wh, g_wh);

    // weight conversion (fp32 -> fp16), 41,370,624 elements
    long long nW = (long long)N_DIM * K_DIM;
    convert_w_kernel<<<(unsigned)((nW / 8 + 255) / 256), 256>>>(wl, wh, nW);

    // frontend: (batch, scale) blocks
    frontend_kernel<<<dim3(2048, 3), 128>>>(x, w1, b1, w2, b2, fa);

    cudaFuncSetAttribute(gemm_relu_kernel,
                         cudaFuncAttributeMaxDynamicSharedMemorySize, SMEM_BYTES);
    dim3 grid((N_DIM + BN - 1) / BN, M_DIM / BM);   // (51, 16)
    gemm_relu_kernel<<<grid, 256, SMEM_BYTES>>>(fa, wh, bl, fb);
    gemm_relu_kernel<<<grid, 256, SMEM_BYTES>>>(fb, wh, bl, fa);
    gemm_relu_kernel<<<grid, 256, SMEM_BYTES>>>(fa, wh, bl, fb);
    gemm_relu_kernel<<<grid, 256, SMEM_BYTES>>>(fb, wh, bl, fa);

    head_kernel<<<2048, 160>>>(fa, wo, bo, out);
}

// round 8
// speedup vs baseline: 1.3830x; 1.1987x over previous
#include <cuda_runtime.h>
#include <cuda_fp16.h>
#include <cuda_bf16.h>
#include <cstdint>

// ---------------------------------------------------------------------------
// InversionModel R8: fp16 mma.sync GEMM, 128x128x32 CTA tiles, 4 warps/CTA,
// warp tile 64x64 (halves crossbar bytes/MMA), double-buffered fragments,
// 2 CTAs/SM (128 threads each, ~215 regs/thread).
// ---------------------------------------------------------------------------

#define BM 128
#define BN 128
#define BK 32
#define STAGES 4
#define LDSK (BK + 8)          // 40 halves per row
#define ALDB (LDSK * 2)        // 80 bytes per smem row
#define M_DIM 2048
#define N_DIM 6432
#define K_DIM 6432
#define SMEM_BYTES (STAGES * (BM + BN) * LDSK * (int)sizeof(__half))   // 81920

// Scratch (static device arrays; no allocation allowed)
__device__ __align__(16) __half g_act0[(size_t)M_DIM * N_DIM];
__device__ __align__(16) __half g_act1[(size_t)M_DIM * N_DIM];
__device__ __align__(16) __half g_wh[(size_t)N_DIM * K_DIM];

// ------------------------------ helpers ------------------------------------

__device__ __forceinline__ void cp16(void* dst, const void* src, bool pred) {
    uint32_t s = (uint32_t)__cvta_generic_to_shared(dst);
    int sz = pred ? 16 : 0;
    asm volatile("cp.async.cg.shared.global [%0], [%1], 16, %2;\n"
                 :: "r"(s), "l"(src), "r"(sz));
}

__device__ __forceinline__ void mma16816(float* c, const uint32_t* a, const uint32_t* b) {
    asm volatile(
        "mma.sync.aligned.m16n8k16.row.col.f32.f16.f16.f32 "
        "{%0,%1,%2,%3}, {%4,%5,%6,%7}, {%8,%9}, {%0,%1,%2,%3};\n"
        : "+f"(c[0]), "+f"(c[1]), "+f"(c[2]), "+f"(c[3])
        : "r"(a[0]), "r"(a[1]), "r"(a[2]), "r"(a[3]), "r"(b[0]), "r"(b[1]));
}

__device__ __forceinline__ void ldsm4(uint32_t& r0, uint32_t& r1, uint32_t& r2,
                                      uint32_t& r3, uint32_t addr) {
    asm volatile("ldmatrix.sync.aligned.m8n8.x4.shared.b16 {%0,%1,%2,%3}, [%4];\n"
                 : "=r"(r0), "=r"(r1), "=r"(r2), "=r"(r3) : "r"(addr));
}

// ------------------------- weight fp32 -> fp16 ------------------------------

__global__ void convert_w_kernel(const float* __restrict__ w, __half* __restrict__ wh,
                                 long long n) {
    long long i = ((long long)blockIdx.x * blockDim.x + threadIdx.x) * 8;
    if (i < n) {
        float4 a = *(const float4*)(w + i);
        float4 b = *(const float4*)(w + i + 4);
        __half2 h0 = __floats2half2_rn(a.x, a.y);
        __half2 h1 = __floats2half2_rn(a.z, a.w);
        __half2 h2 = __floats2half2_rn(b.x, b.y);
        __half2 h3 = __floats2half2_rn(b.z, b.w);
        *(uint4*)(wh + i) = make_uint4(*(uint32_t*)&h0, *(uint32_t*)&h1,
                                       *(uint32_t*)&h2, *(uint32_t*)&h3);
    }
}

// ------------------------------ frontend -----------------------------------

__global__ void frontend_kernel(const float* __restrict__ x,
                                const float* __restrict__ w1, const float* __restrict__ b1,
                                const float* __restrict__ w2, const float* __restrict__ b2,
                                __half* __restrict__ f) {
    int b = blockIdx.x;
    int sidx = blockIdx.y;           // 0,1,2 -> s = 1,2,4
    int s = 1 << sidx;
    int Lc = 480 >> sidx;
    int off = (sidx == 0) ? 0 : (sidx == 1 ? 117 : 174);

    __shared__ float xc[4 * 480];
    __shared__ float p1[16 * 238];
    __shared__ float w1s[320], w2s[2560];
    __shared__ float b1s[16], b2s[32];

    int tid = threadIdx.x;           // 128 threads
    for (int i = tid; i < 320; i += 128) w1s[i] = w1[i];
    for (int i = tid; i < 2560; i += 128) w2s[i] = w2[i];
    if (tid < 16) b1s[tid] = b1[tid];
    if (tid < 32) b2s[tid] = b2[tid];

    const float* xb = x + (size_t)b * 4 * 480;
    float inv_s = 1.0f / (float)s;
    for (int i = tid; i < 4 * Lc; i += 128) {
        int c = i / Lc, p = i % Lc;
        float sum = 0.f;
        for (int j = 0; j < s; ++j) sum += xb[c * 480 + p * s + j];
        xc[c * Lc + p] = sum * inv_s;
    }
    __syncthreads();

    int L1 = Lc - 4;
    int L1p = L1 >> 1;               // 238 / 118 / 58
    for (int i = tid; i < 16 * L1p; i += 128) {
        int o = i / L1p, q = i % L1p;
        float best = -1e30f;
        #pragma unroll
        for (int pp = 0; pp < 2; ++pp) {
            int p = 2 * q + pp;
            float acc = b1s[o];
            #pragma unroll
            for (int c = 0; c < 4; ++c)
                #pragma unroll
                for (int k = 0; k < 5; ++k)
                    acc += xc[c * Lc + p + k] * w1s[o * 20 + c * 5 + k];
            best = fmaxf(best, acc);
        }
        p1[o * L1p + q] = fmaxf(best, 0.f);
    }
    __syncthreads();

    int L2 = (L1p - 4) >> 1;         // 117 / 57 / 27
    __half* fb = f + (size_t)b * N_DIM;
    for (int i = tid; i < 32 * L2; i += 128) {
        int o2 = i / L2, q = i % L2;
        float best = -1e30f;
        #pragma unroll
        for (int pp = 0; pp < 2; ++pp) {
            int p = 2 * q + pp;
            float acc = b2s[o2];
            #pragma unroll
            for (int c1 = 0; c1 < 16; ++c1)
                #pragma unroll
                for (int k = 0; k < 5; ++k)
                    acc += p1[c1 * L1p + p + k] * w2s[o2 * 80 + c1 * 5 + k];
            best = fmaxf(best, acc);
        }
        fb[o2 * 201 + off + q] = __float2half_rn(fmaxf(best, 0.f));
    }
}

// ------------------------------- GEMM --------------------------------------
// Out[m,n] = relu( sum_k A[m,k]*W[n,k] + bias[n] ), fp16 in, fp32 acc, fp16 out.
// 128x128x32 tiles, 4 warps (2x2), warp tile 64x64, double-buffered fragments.

extern __shared__ __half dynsmem[];

__global__ __launch_bounds__(128, 2)
void gemm_relu_kernel(const __half* __restrict__ A, const __half* __restrict__ W,
                      const float* __restrict__ bias, __half* __restrict__ Out) {
    __half* sA = dynsmem;                                  // [STAGES][BM][LDSK]
    __half* sB = dynsmem + STAGES * BM * LDSK;             // [STAGES][BN][LDSK]
#define AS(st, r, c) sA[((st) * BM + (r)) * LDSK + (c)]
#define BS(st, r, c) sB[((st) * BN + (r)) * LDSK + (c)]

    const int tid = threadIdx.x;
    const int bm = blockIdx.y * BM;
    const int bn = blockIdx.x * BN;
    const int warp = tid >> 5, lane = tid & 31;
    const int wm = (warp >> 1) * 64;     // 0 or 64
    const int wn = (warp & 1) * 64;      // 0 or 64
    const int g = lane >> 2, tg = lane & 3;

    const int lr = tid >> 2;            // 0..31
    const int lc = (tid & 3) * 8;       // 0,8,16,24

    // A rows lr+32*i (i=0..3); B rows bn+lr+32*i with clamp+pred
    const __half* Ag = A + (size_t)(bm + lr) * K_DIM + lc;
    const size_t R32 = (size_t)32 * K_DIM;
    bool bv[4];
    const __half* Wg[4];
    #pragma unroll
    for (int i = 0; i < 4; ++i) {
        int nrow = bn + lr + 32 * i;
        bv[i] = nrow < N_DIM;
        Wg[i] = W + (size_t)(bv[i] ? nrow : N_DIM - 1) * K_DIM + lc;
    }

#define LOAD_STAGE(st, k0) do {                                        \
        _Pragma("unroll")                                              \
        for (int _i = 0; _i < 4; ++_i)                                 \
            cp16(&AS(st, lr + 32 * _i, lc), Ag + _i * R32 + (k0), true); \
        _Pragma("unroll")                                              \
        for (int _i = 0; _i < 4; ++_i)                                 \
            cp16(&BS(st, lr + 32 * _i, lc), Wg[_i] + (k0), bv[_i]);    \
    } while (0)

    // ldmatrix per-lane base offsets (bytes, shared space)
    const uint32_t sAu = (uint32_t)__cvta_generic_to_shared(sA);
    const uint32_t sBu = (uint32_t)__cvta_generic_to_shared(sB);
    const uint32_t a_off = (uint32_t)((wm + (lane & 15)) * ALDB + (lane >> 4) * 16);
    const uint32_t b_off = (uint32_t)((wn + (lane >> 4) * 8 + (lane & 7)) * ALDB
                                      + ((lane >> 3) & 1) * 16);

    // Fragment loads for one k-halftile (16 K): 4 A-ldsm4 + 4 B-ldsm4
#define LD_FRAGS(buf, aaddr, baddr) do {                                       \
        _Pragma("unroll")                                                      \
        for (int _mt = 0; _mt < 4; ++_mt)                                      \
            ldsm4(afr[buf][_mt][0], afr[buf][_mt][1], afr[buf][_mt][2],        \
                  afr[buf][_mt][3], (aaddr) + _mt * 16 * ALDB);                \
        _Pragma("unroll")                                                      \
        for (int _p = 0; _p < 4; ++_p)                                         \
            ldsm4(bfr[buf][2 * _p][0], bfr[buf][2 * _p][1],                    \
                  bfr[buf][2 * _p + 1][0], bfr[buf][2 * _p + 1][1],            \
                  (baddr) + _p * 16 * ALDB);                                   \
    } while (0)

#define MMA_BATCH(buf) do {                                                    \
        _Pragma("unroll")                                                      \
        for (int _mt = 0; _mt < 4; ++_mt)                                      \
            _Pragma("unroll")                                                  \
            for (int _nt = 0; _nt < 8; ++_nt)                                  \
                mma16816(acc[_mt][_nt], afr[buf][_mt], bfr[buf][_nt]);         \
    } while (0)

    float acc[4][8][4];
    #pragma unroll
    for (int mt = 0; mt < 4; ++mt)
        #pragma unroll
        for (int nt = 0; nt < 8; ++nt)
            #pragma unroll
            for (int i = 0; i < 4; ++i) acc[mt][nt][i] = 0.f;

    uint32_t afr[2][4][4], bfr[2][8][2];

    // prologue: fill stages 0..2
    #pragma unroll
    for (int st = 0; st < STAGES - 1; ++st) {
        LOAD_STAGE(st, st * BK);
        asm volatile("cp.async.commit_group;\n");
    }
    asm volatile("cp.async.wait_group %0;\n" :: "n"(STAGES - 2));
    __syncthreads();

    uint32_t aS = sAu + a_off;          // stage 0
    uint32_t bS = sBu + b_off;
    LD_FRAGS(0, aS, bS);                // tile 0, ks=0

    const int NK = K_DIM / BK;   // 201
    int st = 0;
    #pragma unroll 1
    for (int kt = 0; kt < NK; ++kt) {
        // ks=1 frags of current tile (one batch ahead)
        LD_FRAGS(1, aS + 32, bS + 32);
        MMA_BATCH(0);

        // issue next stage's global loads
        int knext = kt + STAGES - 1;
        if (knext < NK) LOAD_STAGE(knext & (STAGES - 1), knext * BK);
        asm volatile("cp.async.commit_group;\n");
        asm volatile("cp.async.wait_group %0;\n" :: "n"(STAGES - 2));
        __syncthreads();

        // prefetch next tile's ks=0 frags (stage st+1 completed by wait above)
        int st1 = (st + 1) & (STAGES - 1);
        uint32_t aS1 = sAu + (uint32_t)(st1 * BM * ALDB) + a_off;
        uint32_t bS1 = sBu + (uint32_t)(st1 * BN * ALDB) + b_off;
        LD_FRAGS(0, aS1, bS1);          // harmless garbage on final iteration
        MMA_BATCH(1);

        st = st1; aS = aS1; bS = bS1;
    }

    // Epilogue: bias + relu + fp16 store
    #pragma unroll
    for (int mt = 0; mt < 4; ++mt) {
        int row = bm + wm + mt * 16 + g;
        #pragma unroll
        for (int nt = 0; nt < 8; ++nt) {
            int col = bn + wn + nt * 8 + tg * 2;
            if (col < N_DIM) {
                float2 bb = *(const float2*)(bias + col);
                float v0a = fmaxf(acc[mt][nt][0] + bb.x, 0.f);
                float v1a = fmaxf(acc[mt][nt][1] + bb.y, 0.f);
                float v2a = fmaxf(acc[mt][nt][2] + bb.x, 0.f);
                float v3a = fmaxf(acc[mt][nt][3] + bb.y, 0.f);
                *(__half2*)(Out + (size_t)row * N_DIM + col)       = __floats2half2_rn(v0a, v1a);
                *(__half2*)(Out + (size_t)(row + 8) * N_DIM + col) = __floats2half2_rn(v2a, v3a);
            }
        }
    }
#undef AS
#undef BS
#undef LOAD_STAGE
#undef LD_FRAGS
#undef MMA_BATCH
}

// ------------------------------- head --------------------------------------

__global__ void head_kernel(const __half* __restrict__ f, const float* __restrict__ wo,
                            const float* __restrict__ bo, float* __restrict__ out) {
    int b = blockIdx.x;
    int w = threadIdx.x >> 5;        // 0..4
    int lane = threadIdx.x & 31;
    const __half* fb = f + (size_t)b * N_DIM;
    const float* wr = wo + (size_t)w * N_DIM;
    float acc = 0.f;
    for (int k = lane * 4; k < N_DIM; k += 128) {
        __half2 h0 = *(const __half2*)(fb + k);
        __half2 h1 = *(const __half2*)(fb + k + 2);
        float4 wv = *(const float4*)(wr + k);
        acc += __half2float(h0.x) * wv.x + __half2float(h0.y) * wv.y
             + __half2float(h1.x) * wv.z + __half2float(h1.y) * wv.w;
    }
    #pragma unroll
    for (int o = 16; o > 0; o >>= 1) acc += __shfl_xor_sync(0xffffffffu, acc, o);
    if (lane == 0) out[b * 5 + w] = acc + bo[w];
}

// ------------------------------ launch -------------------------------------

extern "C" void kernel_launch(void* const* d_in, const int* in_sizes, int n_in,
                              void* d_out, int out_size) {
    (void)in_sizes; (void)n_in; (void)out_size;
    const float* x  = (const float*)d_in[0];
    const float* w1 = (const float*)d_in[1];
    const float* b1 = (const float*)d_in[2];
    const float* w2 = (const float*)d_in[3];
    const float* b2 = (const float*)d_in[4];
    const float* wl = (const float*)d_in[5];
    const float* bl = (const float*)d_in[6];
    const float* wo = (const float*)d_in[7];
    const float* bo = (const float*)d_in[8];
    float* out = (float*)d_out;

    __half *fa, *fb, *wh;
    cudaGetSymbolAddress((void**)&fa, g_act0);
    cudaGetSymbolAddress((void**)&fb, g_act1);
    cudaGetSymbolAddress((void**)&wh, g_wh);

    // weight conversion (fp32 -> fp16), 41,370,624 elements
    long long nW = (long long)N_DIM * K_DIM;
    convert_w_kernel<<<(unsigned)((nW / 8 + 255) / 256), 256>>>(wl, wh, nW);

    // frontend: (batch, scale) blocks
    frontend_kernel<<<dim3(2048, 3), 128>>>(x, w1, b1, w2, b2, fa);

    cudaFuncSetAttribute(gemm_relu_kernel,
                         cudaFuncAttributeMaxDynamicSharedMemorySize, SMEM_BYTES);
    dim3 grid((N_DIM + BN - 1) / BN, M_DIM / BM);   // (51, 16)
    gemm_relu_kernel<<<grid, 128, SMEM_BYTES>>>(fa, wh, bl, fb);
    gemm_relu_kernel<<<grid, 128, SMEM_BYTES>>>(fb, wh, bl, fa);
    gemm_relu_kernel<<<grid, 128, SMEM_BYTES>>>(fa, wh, bl, fb);
    gemm_relu_kernel<<<grid, 128, SMEM_BYTES>>>(fb, wh, bl, fa);

    head_kernel<<<2048, 160>>>(fa, wo, bo, out);
}

// round 9
// speedup vs baseline: 1.5387x; 1.1126x over previous
#include <cuda_runtime.h>
#include <cuda_fp16.h>
#include <cuda_bf16.h>
#include <cstdint>

// ---------------------------------------------------------------------------
// InversionModel R9: GEMM identical to R8 (402us, tensor 70%).
// Frontend rewritten: weights in registers, float2 windows, 4 acc chains
// (LDS/FMA cut ~6x). Weight fp32->fp16 convert fused into the same launch.
// ---------------------------------------------------------------------------

#define BM 128
#define BN 128
#define BK 32
#define STAGES 4
#define LDSK (BK + 8)          // 40 halves per row
#define ALDB (LDSK * 2)        // 80 bytes per smem row
#define M_DIM 2048
#define N_DIM 6432
#define K_DIM 6432
#define SMEM_BYTES (STAGES * (BM + BN) * LDSK * (int)sizeof(__half))   // 81920

#define FE_BLOCKS 6144                       // 2048 batches x 3 scales
#define NW ((long long)N_DIM * K_DIM)        // 41,370,624
#define CONV_BLOCKS ((int)((NW + 1023) / 1024))   // 128 thr x 8 elems

// Scratch (static device arrays; no allocation allowed)
__device__ __align__(16) __half g_act0[(size_t)M_DIM * N_DIM];
__device__ __align__(16) __half g_act1[(size_t)M_DIM * N_DIM];
__device__ __align__(16) __half g_wh[(size_t)N_DIM * K_DIM];

// ------------------------------ helpers ------------------------------------

__device__ __forceinline__ void cp16(void* dst, const void* src, bool pred) {
    uint32_t s = (uint32_t)__cvta_generic_to_shared(dst);
    int sz = pred ? 16 : 0;
    asm volatile("cp.async.cg.shared.global [%0], [%1], 16, %2;\n"
                 :: "r"(s), "l"(src), "r"(sz));
}

__device__ __forceinline__ void mma16816(float* c, const uint32_t* a, const uint32_t* b) {
    asm volatile(
        "mma.sync.aligned.m16n8k16.row.col.f32.f16.f16.f32 "
        "{%0,%1,%2,%3}, {%4,%5,%6,%7}, {%8,%9}, {%0,%1,%2,%3};\n"
        : "+f"(c[0]), "+f"(c[1]), "+f"(c[2]), "+f"(c[3])
        : "r"(a[0]), "r"(a[1]), "r"(a[2]), "r"(a[3]), "r"(b[0]), "r"(b[1]));
}

__device__ __forceinline__ void ldsm4(uint32_t& r0, uint32_t& r1, uint32_t& r2,
                                      uint32_t& r3, uint32_t addr) {
    asm volatile("ldmatrix.sync.aligned.m8n8.x4.shared.b16 {%0,%1,%2,%3}, [%4];\n"
                 : "=r"(r0), "=r"(r1), "=r"(r2), "=r"(r3) : "r"(addr));
}

// ----------------- fused prep: frontend + weight convert --------------------
// blocks [0, FE_BLOCKS)           : conv frontend, one (batch, scale) each
// blocks [FE_BLOCKS, +CONV_BLOCKS): fp32->fp16 weight conversion (8 elem/thr)

__global__ void prep_kernel(const float* __restrict__ x,
                            const float* __restrict__ w1, const float* __restrict__ b1,
                            const float* __restrict__ w2, const float* __restrict__ b2,
                            __half* __restrict__ f,
                            const float* __restrict__ wl, __half* __restrict__ wh) {
    if (blockIdx.x >= FE_BLOCKS) {
        long long i = ((long long)(blockIdx.x - FE_BLOCKS) * 128 + threadIdx.x) * 8;
        if (i < NW) {
            float4 a = *(const float4*)(wl + i);
            float4 b = *(const float4*)(wl + i + 4);
            __half2 h0 = __floats2half2_rn(a.x, a.y);
            __half2 h1 = __floats2half2_rn(a.z, a.w);
            __half2 h2 = __floats2half2_rn(b.x, b.y);
            __half2 h3 = __floats2half2_rn(b.z, b.w);
            *(uint4*)(wh + i) = make_uint4(*(uint32_t*)&h0, *(uint32_t*)&h1,
                                           *(uint32_t*)&h2, *(uint32_t*)&h3);
        }
        return;
    }

    int b = blockIdx.x & 2047;
    int sidx = blockIdx.x >> 11;     // 0,1,2 -> s = 1,2,4
    int s = 1 << sidx;
    int Lc = 480 >> sidx;
    int off = (sidx == 0) ? 0 : (sidx == 1 ? 117 : 174);

    __shared__ float xc[4 * 480];
    __shared__ float p1[16 * 238];
    __shared__ float w1s[320], w2s[2560];
    __shared__ float b1s[16], b2s[32];

    int tid = threadIdx.x;           // 128 threads
    for (int i = tid; i < 320; i += 128) w1s[i] = w1[i];
    for (int i = tid; i < 2560; i += 128) w2s[i] = w2[i];
    if (tid < 16) b1s[tid] = b1[tid];
    if (tid < 32) b2s[tid] = b2[tid];

    // coarse grain into smem
    const float* xb = x + (size_t)b * 4 * 480;
    float inv_s = 1.0f / (float)s;
    for (int i = tid; i < 4 * Lc; i += 128) {
        int c = i / Lc, p = i % Lc;
        float sum = 0.f;
        for (int j = 0; j < s; ++j) sum += xb[c * 480 + p * s + j];
        xc[c * Lc + p] = sum * inv_s;
    }
    __syncthreads();

    // conv1 + relu + pool: thread = (channel o = tid&15, chunk = tid>>4 of 8)
    int L1p = (Lc - 4) >> 1;         // 238 / 118 / 58
    {
        int o = tid & 15, ch = tid >> 4;
        float w1r[20];
        #pragma unroll
        for (int i = 0; i < 20; ++i) w1r[i] = w1s[o * 20 + i];
        float b1r = b1s[o];
        for (int q = ch; q < L1p; q += 8) {
            float a0 = b1r, a1 = b1r;
            #pragma unroll
            for (int c = 0; c < 4; ++c) {
                const float2* xp = (const float2*)&xc[c * Lc + 2 * q];
                float2 v0 = xp[0], v1 = xp[1], v2 = xp[2];
                const float* w = &w1r[c * 5];
                a0 = fmaf(v0.x, w[0], a0);
                a0 = fmaf(v0.y, w[1], a0);
                a0 = fmaf(v1.x, w[2], a0);
                a0 = fmaf(v1.y, w[3], a0);
                a0 = fmaf(v2.x, w[4], a0);
                a1 = fmaf(v0.y, w[0], a1);
                a1 = fmaf(v1.x, w[1], a1);
                a1 = fmaf(v1.y, w[2], a1);
                a1 = fmaf(v2.x, w[3], a1);
                a1 = fmaf(v2.y, w[4], a1);
            }
            p1[o * L1p + q] = fmaxf(fmaxf(a0, a1), 0.f);
        }
    }
    __syncthreads();

    // conv2 + relu + pool: thread = (channel o2 = tid&31, chunk = tid>>5 of 4)
    int L2 = (L1p - 4) >> 1;         // 117 / 57 / 27
    {
        int o2 = tid & 31, ch2 = tid >> 5;
        float w2r[80];
        #pragma unroll
        for (int i = 0; i < 80; ++i) w2r[i] = w2s[o2 * 80 + i];
        float b2r = b2s[o2];
        __half* fb = f + (size_t)b * N_DIM;
        for (int q = ch2; q < L2; q += 4) {
            // 4 accumulation chains: (pos0/pos1) x (even/odd c1)
            float a0 = b2r, a1 = b2r, a0b = 0.f, a1b = 0.f;
            #pragma unroll
            for (int c1 = 0; c1 < 16; ++c1) {
                const float2* pp = (const float2*)&p1[c1 * L1p + 2 * q];
                float2 v0 = pp[0], v1 = pp[1], v2 = pp[2];
                const float* w = &w2r[c1 * 5];
                if (c1 & 1) {
                    a0b = fmaf(v0.x, w[0], a0b);
                    a0b = fmaf(v0.y, w[1], a0b);
                    a0b = fmaf(v1.x, w[2], a0b);
                    a0b = fmaf(v1.y, w[3], a0b);
                    a0b = fmaf(v2.x, w[4], a0b);
                    a1b = fmaf(v0.y, w[0], a1b);
                    a1b = fmaf(v1.x, w[1], a1b);
                    a1b = fmaf(v1.y, w[2], a1b);
                    a1b = fmaf(v2.x, w[3], a1b);
                    a1b = fmaf(v2.y, w[4], a1b);
                } else {
                    a0 = fmaf(v0.x, w[0], a0);
                    a0 = fmaf(v0.y, w[1], a0);
                    a0 = fmaf(v1.x, w[2], a0);
                    a0 = fmaf(v1.y, w[3], a0);
                    a0 = fmaf(v2.x, w[4], a0);
                    a1 = fmaf(v0.y, w[0], a1);
                    a1 = fmaf(v1.x, w[1], a1);
                    a1 = fmaf(v1.y, w[2], a1);
                    a1 = fmaf(v2.x, w[3], a1);
                    a1 = fmaf(v2.y, w[4], a1);
                }
            }
            float r = fmaxf(fmaxf(a0 + a0b, a1 + a1b), 0.f);
            fb[o2 * 201 + off + q] = __float2half_rn(r);
        }
    }
}

// ------------------------------- GEMM (R8, unchanged) -----------------------
// Out[m,n] = relu( sum_k A[m,k]*W[n,k] + bias[n] ), fp16 in, fp32 acc, fp16 out.
// 128x128x32 tiles, 4 warps (2x2), warp tile 64x64, double-buffered fragments.

extern __shared__ __half dynsmem[];

__global__ __launch_bounds__(128, 2)
void gemm_relu_kernel(const __half* __restrict__ A, const __half* __restrict__ W,
                      const float* __restrict__ bias, __half* __restrict__ Out) {
    __half* sA = dynsmem;                                  // [STAGES][BM][LDSK]
    __half* sB = dynsmem + STAGES * BM * LDSK;             // [STAGES][BN][LDSK]
#define AS(st, r, c) sA[((st) * BM + (r)) * LDSK + (c)]
#define BS(st, r, c) sB[((st) * BN + (r)) * LDSK + (c)]

    const int tid = threadIdx.x;
    const int bm = blockIdx.y * BM;
    const int bn = blockIdx.x * BN;
    const int warp = tid >> 5, lane = tid & 31;
    const int wm = (warp >> 1) * 64;     // 0 or 64
    const int wn = (warp & 1) * 64;      // 0 or 64
    const int g = lane >> 2, tg = lane & 3;

    const int lr = tid >> 2;            // 0..31
    const int lc = (tid & 3) * 8;       // 0,8,16,24

    const __half* Ag = A + (size_t)(bm + lr) * K_DIM + lc;
    const size_t R32 = (size_t)32 * K_DIM;
    bool bv[4];
    const __half* Wg[4];
    #pragma unroll
    for (int i = 0; i < 4; ++i) {
        int nrow = bn + lr + 32 * i;
        bv[i] = nrow < N_DIM;
        Wg[i] = W + (size_t)(bv[i] ? nrow : N_DIM - 1) * K_DIM + lc;
    }

#define LOAD_STAGE(st, k0) do {                                        \
        _Pragma("unroll")                                              \
        for (int _i = 0; _i < 4; ++_i)                                 \
            cp16(&AS(st, lr + 32 * _i, lc), Ag + _i * R32 + (k0), true); \
        _Pragma("unroll")                                              \
        for (int _i = 0; _i < 4; ++_i)                                 \
            cp16(&BS(st, lr + 32 * _i, lc), Wg[_i] + (k0), bv[_i]);    \
    } while (0)

    const uint32_t sAu = (uint32_t)__cvta_generic_to_shared(sA);
    const uint32_t sBu = (uint32_t)__cvta_generic_to_shared(sB);
    const uint32_t a_off = (uint32_t)((wm + (lane & 15)) * ALDB + (lane >> 4) * 16);
    const uint32_t b_off = (uint32_t)((wn + (lane >> 4) * 8 + (lane & 7)) * ALDB
                                      + ((lane >> 3) & 1) * 16);

#define LD_FRAGS(buf, aaddr, baddr) do {                                       \
        _Pragma("unroll")                                                      \
        for (int _mt = 0; _mt < 4; ++_mt)                                      \
            ldsm4(afr[buf][_mt][0], afr[buf][_mt][1], afr[buf][_mt][2],        \
                  afr[buf][_mt][3], (aaddr) + _mt * 16 * ALDB);                \
        _Pragma("unroll")                                                      \
        for (int _p = 0; _p < 4; ++_p)                                         \
            ldsm4(bfr[buf][2 * _p][0], bfr[buf][2 * _p][1],                    \
                  bfr[buf][2 * _p + 1][0], bfr[buf][2 * _p + 1][1],            \
                  (baddr) + _p * 16 * ALDB);                                   \
    } while (0)

#define MMA_BATCH(buf) do {                                                    \
        _Pragma("unroll")                                                      \
        for (int _mt = 0; _mt < 4; ++_mt)                                      \
            _Pragma("unroll")                                                  \
            for (int _nt = 0; _nt < 8; ++_nt)                                  \
                mma16816(acc[_mt][_nt], afr[buf][_mt], bfr[buf][_nt]);         \
    } while (0)

    float acc[4][8][4];
    #pragma unroll
    for (int mt = 0; mt < 4; ++mt)
        #pragma unroll
        for (int nt = 0; nt < 8; ++nt)
            #pragma unroll
            for (int i = 0; i < 4; ++i) acc[mt][nt][i] = 0.f;

    uint32_t afr[2][4][4], bfr[2][8][2];

    #pragma unroll
    for (int st = 0; st < STAGES - 1; ++st) {
        LOAD_STAGE(st, st * BK);
        asm volatile("cp.async.commit_group;\n");
    }
    asm volatile("cp.async.wait_group %0;\n" :: "n"(STAGES - 2));
    __syncthreads();

    uint32_t aS = sAu + a_off;          // stage 0
    uint32_t bS = sBu + b_off;
    LD_FRAGS(0, aS, bS);                // tile 0, ks=0

    const int NK = K_DIM / BK;   // 201
    int st = 0;
    #pragma unroll 1
    for (int kt = 0; kt < NK; ++kt) {
        LD_FRAGS(1, aS + 32, bS + 32);
        MMA_BATCH(0);

        int knext = kt + STAGES - 1;
        if (knext < NK) LOAD_STAGE(knext & (STAGES - 1), knext * BK);
        asm volatile("cp.async.commit_group;\n");
        asm volatile("cp.async.wait_group %0;\n" :: "n"(STAGES - 2));
        __syncthreads();

        int st1 = (st + 1) & (STAGES - 1);
        uint32_t aS1 = sAu + (uint32_t)(st1 * BM * ALDB) + a_off;
        uint32_t bS1 = sBu + (uint32_t)(st1 * BN * ALDB) + b_off;
        LD_FRAGS(0, aS1, bS1);          // harmless garbage on final iteration
        MMA_BATCH(1);

        st = st1; aS = aS1; bS = bS1;
    }

    #pragma unroll
    for (int mt = 0; mt < 4; ++mt) {
        int row = bm + wm + mt * 16 + g;
        #pragma unroll
        for (int nt = 0; nt < 8; ++nt) {
            int col = bn + wn + nt * 8 + tg * 2;
            if (col < N_DIM) {
                float2 bb = *(const float2*)(bias + col);
                float v0a = fmaxf(acc[mt][nt][0] + bb.x, 0.f);
                float v1a = fmaxf(acc[mt][nt][1] + bb.y, 0.f);
                float v2a = fmaxf(acc[mt][nt][2] + bb.x, 0.f);
                float v3a = fmaxf(acc[mt][nt][3] + bb.y, 0.f);
                *(__half2*)(Out + (size_t)row * N_DIM + col)       = __floats2half2_rn(v0a, v1a);
                *(__half2*)(Out + (size_t)(row + 8) * N_DIM + col) = __floats2half2_rn(v2a, v3a);
            }
        }
    }
#undef AS
#undef BS
#undef LOAD_STAGE
#undef LD_FRAGS
#undef MMA_BATCH
}

// ------------------------------- head --------------------------------------

__global__ void head_kernel(const __half* __restrict__ f, const float* __restrict__ wo,
                            const float* __restrict__ bo, float* __restrict__ out) {
    int b = blockIdx.x;
    int w = threadIdx.x >> 5;        // 0..4
    int lane = threadIdx.x & 31;
    const __half* fb = f + (size_t)b * N_DIM;
    const float* wr = wo + (size_t)w * N_DIM;
    float acc = 0.f;
    for (int k = lane * 4; k < N_DIM; k += 128) {
        __half2 h0 = *(const __half2*)(fb + k);
        __half2 h1 = *(const __half2*)(fb + k + 2);
        float4 wv = *(const float4*)(wr + k);
        acc += __half2float(h0.x) * wv.x + __half2float(h0.y) * wv.y
             + __half2float(h1.x) * wv.z + __half2float(h1.y) * wv.w;
    }
    #pragma unroll
    for (int o = 16; o > 0; o >>= 1) acc += __shfl_xor_sync(0xffffffffu, acc, o);
    if (lane == 0) out[b * 5 + w] = acc + bo[w];
}

// ------------------------------ launch -------------------------------------

extern "C" void kernel_launch(void* const* d_in, const int* in_sizes, int n_in,
                              void* d_out, int out_size) {
    (void)in_sizes; (void)n_in; (void)out_size;
    const float* x  = (const float*)d_in[0];
    const float* w1 = (const float*)d_in[1];
    const float* b1 = (const float*)d_in[2];
    const float* w2 = (const float*)d_in[3];
    const float* b2 = (const float*)d_in[4];
    const float* wl = (const float*)d_in[5];
    const float* bl = (const float*)d_in[6];
    const float* wo = (const float*)d_in[7];
    const float* bo = (const float*)d_in[8];
    float* out = (float*)d_out;

    __half *fa, *fb, *wh;
    cudaGetSymbolAddress((void**)&fa, g_act0);
    cudaGetSymbolAddress((void**)&fb, g_act1);
    cudaGetSymbolAddress((void**)&wh, g_wh);

    // fused frontend + weight conversion
    prep_kernel<<<FE_BLOCKS + CONV_BLOCKS, 128>>>(x, w1, b1, w2, b2, fa, wl, wh);

    cudaFuncSetAttribute(gemm_relu_kernel,
                         cudaFuncAttributeMaxDynamicSharedMemorySize, SMEM_BYTES);
    dim3 grid((N_DIM + BN - 1) / BN, M_DIM / BM);   // (51, 16)
    gemm_relu_kernel<<<grid, 128, SMEM_BYTES>>>(fa, wh, bl, fb);
    gemm_relu_kernel<<<grid, 128, SMEM_BYTES>>>(fb, wh, bl, fa);
    gemm_relu_kernel<<<grid, 128, SMEM_BYTES>>>(fa, wh, bl, fb);
    gemm_relu_kernel<<<grid, 128, SMEM_BYTES>>>(fb, wh, bl, fa);

    head_kernel<<<2048, 160>>>(fa, wo, bo, out);
}